// round 7
// baseline (speedup 1.0000x reference)
#include <cuda_runtime.h>
#include <cuda_bf16.h>
#include <cstdint>

// ---------------------------------------------------------------------------
// Shapes
// ---------------------------------------------------------------------------
#define NB   32
#define HW   4096
#define FC   256
#define OD   128
#define O2   256
#define HSP  128
#define NT   8
#define SPLIT 4

#define DENSE_TOTAL ((size_t)NB * O2 * HW)

// ---------------------------------------------------------------------------
// Scratch (device globals; 16B-aligned)
// ---------------------------------------------------------------------------
__device__ __align__(16) unsigned short g_fh[(size_t)NB * HW * FC];
__device__ __align__(16) unsigned short g_fl[(size_t)NB * HW * FC];
__device__ __align__(16) unsigned short g_w1h[OD * FC],  g_w1l[OD * FC];
__device__ __align__(16) unsigned short g_w2h[O2 * OD],  g_w2l[O2 * OD];
__device__ __align__(16) unsigned short g_ws1h[HSP * HW], g_ws1l[HSP * HW];
__device__ float g_hsp[(size_t)SPLIT * NB * FC * HSP];   // [ks][bb][c][o]

// ---------------------------------------------------------------------------
// Helpers
// ---------------------------------------------------------------------------
__device__ __forceinline__ uint32_t s2u(const void* p) {
    uint32_t a;
    asm("{ .reg .u64 t; cvta.to.shared.u64 t, %1; cvt.u32.u64 %0, t; }" : "=r"(a) : "l"(p));
    return a;
}

#define LDSM4(r0, r1, r2, r3, addr)                                              \
    asm volatile("ldmatrix.sync.aligned.m8n8.x4.shared.b16 {%0,%1,%2,%3}, [%4];" \
                 : "=r"(r0), "=r"(r1), "=r"(r2), "=r"(r3) : "r"(addr))
#define LDSM4T(r0, r1, r2, r3, addr)                                                   \
    asm volatile("ldmatrix.sync.aligned.m8n8.x4.trans.shared.b16 {%0,%1,%2,%3}, [%4];" \
                 : "=r"(r0), "=r"(r1), "=r"(r2), "=r"(r3) : "r"(addr))

#define CPA16(dst, src) \
    asm volatile("cp.async.cg.shared.global [%0], [%1], 16;" :: "r"(dst), "l"(src))
#define CPA_COMMIT() asm volatile("cp.async.commit_group;" ::: "memory")
#define CPA_WAIT(n)  asm volatile("cp.async.wait_group %0;" :: "n"(n) : "memory")

__device__ __forceinline__ void mma_bf(float* c, const uint32_t* a,
                                       uint32_t b0, uint32_t b1) {
    asm volatile(
        "mma.sync.aligned.m16n8k16.row.col.f32.bf16.bf16.f32 "
        "{%0,%1,%2,%3},{%4,%5,%6,%7},{%8,%9},{%0,%1,%2,%3};"
        : "+f"(c[0]), "+f"(c[1]), "+f"(c[2]), "+f"(c[3])
        : "r"(a[0]), "r"(a[1]), "r"(a[2]), "r"(a[3]), "r"(b0), "r"(b1));
}

__device__ __forceinline__ void hilo(float x, unsigned short& h, unsigned short& l) {
    __nv_bfloat16 bh = __float2bfloat16_rn(x);
    h = __bfloat16_as_ushort(bh);
    l = __bfloat16_as_ushort(__float2bfloat16_rn(x - __bfloat162float(bh)));
}
__device__ __forceinline__ void hilo4(float a, float b, float c, float d,
                                      ushort4& h4, ushort4& l4) {
    hilo(a, h4.x, l4.x); hilo(b, h4.y, l4.y); hilo(c, h4.z, l4.z); hilo(d, h4.w, l4.w);
}

// ---------------------------------------------------------------------------
// K0: featprep — fused scale + bf16 hi/lo split (warp per pixel)
// ---------------------------------------------------------------------------
__global__ void k_featprep(const float* __restrict__ feat, const float* __restrict__ proto)
{
    __shared__ float pr[FC];
    const int t = threadIdx.x;
    pr[t] = proto[t];
    __syncthreads();
    const int warp = t >> 5, lane = t & 31;
    const int pix = blockIdx.x * 8 + warp;
    const float4* f4 = reinterpret_cast<const float4*>(feat + (size_t)pix * FC);
    float4 a = f4[lane];
    float4 b = f4[lane + 32];
    const int c0 = lane * 4;
    float s = a.x*pr[c0] + a.y*pr[c0+1] + a.z*pr[c0+2] + a.w*pr[c0+3]
            + b.x*pr[128+c0] + b.y*pr[128+c0+1] + b.z*pr[128+c0+2] + b.w*pr[128+c0+3];
    #pragma unroll
    for (int off = 16; off > 0; off >>= 1) s += __shfl_xor_sync(0xFFFFFFFFu, s, off);
    s += 1.0f;
    ushort4 h4, l4;
    hilo4(a.x * s, a.y * s, a.z * s, a.w * s, h4, l4);
    reinterpret_cast<ushort4*>(g_fh + (size_t)pix * FC)[lane] = h4;
    reinterpret_cast<ushort4*>(g_fl + (size_t)pix * FC)[lane] = l4;
    hilo4(b.x * s, b.y * s, b.z * s, b.w * s, h4, l4);
    reinterpret_cast<ushort4*>(g_fh + (size_t)pix * FC)[lane + 32] = h4;
    reinterpret_cast<ushort4*>(g_fl + (size_t)pix * FC)[lane + 32] = l4;
}

// ---------------------------------------------------------------------------
// K1: split weights into bf16 hi/lo
// ---------------------------------------------------------------------------
__global__ void k_prep(const float* __restrict__ w_d1, const float* __restrict__ w_d2,
                       const float* __restrict__ w_s1)
{
    const int q = blockIdx.x * 256 + threadIdx.x;
    const float4* src;
    ushort4 *dh, *dl;
    int idx;
    if (q < 8192) {
        src = reinterpret_cast<const float4*>(w_d1);  idx = q;
        dh = reinterpret_cast<ushort4*>(g_w1h);  dl = reinterpret_cast<ushort4*>(g_w1l);
    } else if (q < 16384) {
        src = reinterpret_cast<const float4*>(w_d2);  idx = q - 8192;
        dh = reinterpret_cast<ushort4*>(g_w2h);  dl = reinterpret_cast<ushort4*>(g_w2l);
    } else {
        idx = q - 16384;
        if (idx >= HSP * HW / 4) return;
        src = reinterpret_cast<const float4*>(w_s1);
        dh = reinterpret_cast<ushort4*>(g_ws1h); dl = reinterpret_cast<ushort4*>(g_ws1l);
    }
    const float4 f = src[idx];
    ushort4 h4, l4;
    hilo4(f.x, f.y, f.z, f.w, h4, l4);
    dh[idx] = h4;  dl[idx] = l4;
}

// ---------------------------------------------------------------------------
// K2: dense path.  3-stage cp.async GEMM1, phase-overlapped GEMM2.
// smem (bytes):
//   GEMM1 stages s=0..2: A hi/lo @ s*73728 + hl*18432; B1 hi/lo @ +36864
//   After GEMM1 (aliases): Hs hi/lo @ 0 + hl*34816; B2 hi/lo @ 73728 + hl*34816
//   STG f32 @ 147456 (67584)
// ---------------------------------------------------------------------------
#define PK 72
#define PH 136
#define PS 132
#define DA3(s, hl) ((s) * 73728 + (hl) * 18432)
#define DB3(s, hl) ((s) * 73728 + 36864 + (hl) * 18432)
#define DHS(hl)    ((hl) * 34816)
#define DB2(hl)    (73728 + (hl) * 34816)
#define DSTG       147456
#define D_SMEM     221184

__global__ void __launch_bounds__(256, 1)
k_dense(const float* __restrict__ b1, const float* __restrict__ b2,
        float* __restrict__ out)
{
    extern __shared__ char smem[];
    const uint32_t sb = s2u(smem);
    const int tid = threadIdx.x, wid = tid >> 5, lane = tid & 31;
    const int bb = blockIdx.x >> 5;
    const int p0 = (blockIdx.x & 31) << 7;
    const size_t fbase = ((size_t)bb * HW + p0) * FC;

    const int wm = (wid >> 1) * 32, wn = (wid & 1) * 64;
    const int lr = lane & 7, lg = lane >> 3;
    const int qrow = lane >> 2, qcol = (lane & 3) * 2;

    float acc[2][8][4];
    #pragma unroll
    for (int mi = 0; mi < 2; ++mi)
        #pragma unroll
        for (int f = 0; f < 8; ++f)
            #pragma unroll
            for (int v = 0; v < 4; ++v) acc[mi][f][v] = 0.f;

    auto fill1 = [&](int kc, int s) {
        #pragma unroll
        for (int i = 0; i < 4; ++i) {
            const int idx = i * 256 + tid;
            const int row = idx >> 3, seg = idx & 7;
            const uint32_t d = row * 144 + seg * 16;
            const size_t fo = fbase + (size_t)row * FC + kc * 64 + seg * 8;
            CPA16(sb + DA3(s, 0) + d, g_fh + fo);
            CPA16(sb + DA3(s, 1) + d, g_fl + fo);
            const int wo = row * FC + kc * 64 + seg * 8;
            CPA16(sb + DB3(s, 0) + d, g_w1h + wo);
            CPA16(sb + DB3(s, 1) + d, g_w1l + wo);
        }
        CPA_COMMIT();
    };

    fill1(0, 0);
    fill1(1, 1);
    #pragma unroll 1
    for (int kc = 0; kc < 4; ++kc) {
        if (kc < 3) { CPA_WAIT(1); } else { CPA_WAIT(0); }
        __syncthreads();
        if (kc + 2 < 4) fill1(kc + 2, (kc + 2) % 3);
        const int s = kc % 3;
        #pragma unroll
        for (int ks = 0; ks < 4; ++ks) {
            const int k0 = ks * 16;
            uint32_t ah[2][4], al[2][4];
            #pragma unroll
            for (int mi = 0; mi < 2; ++mi) {
                const uint32_t ad = sb + 2 * ((wm + mi * 16 + lr + ((lg & 1) << 3)) * PK + k0 + ((lg >> 1) << 3));
                LDSM4(ah[mi][0], ah[mi][1], ah[mi][2], ah[mi][3], ad + DA3(s, 0));
                LDSM4(al[mi][0], al[mi][1], al[mi][2], al[mi][3], ad + DA3(s, 1));
            }
            #pragma unroll
            for (int nf = 0; nf < 4; ++nf) {
                uint32_t bh[4], bl[4];
                const uint32_t bd = sb + 2 * ((wn + nf * 16 + lr + ((lg >> 1) << 3)) * PK + k0 + ((lg & 1) << 3));
                LDSM4(bh[0], bh[1], bh[2], bh[3], bd + DB3(s, 0));
                LDSM4(bl[0], bl[1], bl[2], bl[3], bd + DB3(s, 1));
                #pragma unroll
                for (int mi = 0; mi < 2; ++mi)
                    #pragma unroll
                    for (int h = 0; h < 2; ++h) {
                        float* c = acc[mi][nf * 2 + h];
                        mma_bf(c, ah[mi], bh[h * 2], bh[h * 2 + 1]);
                        mma_bf(c, ah[mi], bl[h * 2], bl[h * 2 + 1]);
                        mma_bf(c, al[mi], bh[h * 2], bh[h * 2 + 1]);
                    }
            }
        }
    }
    __syncthreads();   // all GEMM1 mma done; stage memory free

    auto fillB2 = [&](int pass) {
        #pragma unroll
        for (int i = 0; i < 8; ++i) {
            const int idx = i * 256 + tid;
            const int row = idx >> 4, seg = idx & 15;
            const uint32_t d = row * 272 + seg * 16;
            const int wo = (pass * 128 + row) * OD + seg * 8;
            CPA16(sb + DB2(0) + d, g_w2h + wo);
            CPA16(sb + DB2(1) + d, g_w2l + wo);
        }
        CPA_COMMIT();
    };
    fillB2(0);   // overlaps epilogue 1

    // epilogue 1: relu(acc + b1) -> Hs hi/lo [128p][128o]
    #pragma unroll
    for (int mi = 0; mi < 2; ++mi)
        #pragma unroll
        for (int f = 0; f < 8; ++f) {
            const int row = wm + mi * 16 + qrow;
            const int col = wn + f * 8 + qcol;
            const float bv0 = __ldg(&b1[col]), bv1 = __ldg(&b1[col + 1]);
            const float v00 = fmaxf(acc[mi][f][0] + bv0, 0.f);
            const float v01 = fmaxf(acc[mi][f][1] + bv1, 0.f);
            const float v10 = fmaxf(acc[mi][f][2] + bv0, 0.f);
            const float v11 = fmaxf(acc[mi][f][3] + bv1, 0.f);
            unsigned short h0, l0, h1, l1;
            hilo(v00, h0, l0); hilo(v01, h1, l1);
            *reinterpret_cast<uint32_t*>(smem + DHS(0) + 2 * (row * PH + col)) = (uint32_t)h0 | ((uint32_t)h1 << 16);
            *reinterpret_cast<uint32_t*>(smem + DHS(1) + 2 * (row * PH + col)) = (uint32_t)l0 | ((uint32_t)l1 << 16);
            hilo(v10, h0, l0); hilo(v11, h1, l1);
            *reinterpret_cast<uint32_t*>(smem + DHS(0) + 2 * ((row + 8) * PH + col)) = (uint32_t)h0 | ((uint32_t)h1 << 16);
            *reinterpret_cast<uint32_t*>(smem + DHS(1) + 2 * ((row + 8) * PH + col)) = (uint32_t)l0 | ((uint32_t)l1 << 16);
        }
    CPA_WAIT(0);
    __syncthreads();

    // GEMM2: two passes of 128 o2, K=128
    #pragma unroll 1
    for (int pass = 0; pass < 2; ++pass) {
        float a2[2][8][4];
        #pragma unroll
        for (int mi = 0; mi < 2; ++mi)
            #pragma unroll
            for (int f = 0; f < 8; ++f)
                #pragma unroll
                for (int v = 0; v < 4; ++v) a2[mi][f][v] = 0.f;

        #pragma unroll
        for (int ks = 0; ks < 8; ++ks) {
            const int k0 = ks * 16;
            uint32_t ah[2][4], al[2][4];
            #pragma unroll
            for (int mi = 0; mi < 2; ++mi) {
                const uint32_t ad = sb + 2 * ((wm + mi * 16 + lr + ((lg & 1) << 3)) * PH + k0 + ((lg >> 1) << 3));
                LDSM4(ah[mi][0], ah[mi][1], ah[mi][2], ah[mi][3], ad + DHS(0));
                LDSM4(al[mi][0], al[mi][1], al[mi][2], al[mi][3], ad + DHS(1));
            }
            #pragma unroll
            for (int nf = 0; nf < 4; ++nf) {
                uint32_t bh[4], bl[4];
                const uint32_t bd = sb + 2 * ((wn + nf * 16 + lr + ((lg >> 1) << 3)) * PH + k0 + ((lg & 1) << 3));
                LDSM4(bh[0], bh[1], bh[2], bh[3], bd + DB2(0));
                LDSM4(bl[0], bl[1], bl[2], bl[3], bd + DB2(1));
                #pragma unroll
                for (int mi = 0; mi < 2; ++mi)
                    #pragma unroll
                    for (int h = 0; h < 2; ++h) {
                        float* c = a2[mi][nf * 2 + h];
                        mma_bf(c, ah[mi], bh[h * 2], bh[h * 2 + 1]);
                        mma_bf(c, ah[mi], bl[h * 2], bl[h * 2 + 1]);
                        mma_bf(c, al[mi], bh[h * 2], bh[h * 2 + 1]);
                    }
            }
        }
        __syncthreads();
        if (pass == 0) fillB2(1);   // overlaps epilogue

        float* stg = reinterpret_cast<float*>(smem + DSTG);
        #pragma unroll
        for (int mi = 0; mi < 2; ++mi)
            #pragma unroll
            for (int f = 0; f < 8; ++f) {
                const int row = wm + mi * 16 + qrow;
                const int col = wn + f * 8 + qcol;
                const float bv0 = __ldg(&b2[pass * 128 + col]);
                const float bv1 = __ldg(&b2[pass * 128 + col + 1]);
                stg[col * PS + row]           = a2[mi][f][0] + bv0;
                stg[(col + 1) * PS + row]     = a2[mi][f][1] + bv1;
                stg[col * PS + row + 8]       = a2[mi][f][2] + bv0;
                stg[(col + 1) * PS + row + 8] = a2[mi][f][3] + bv1;
            }
        __syncthreads();

        float* ob = out + (size_t)bb * O2 * HW + (size_t)(pass * 128) * HW + p0;
        const int row = tid >> 1, off = (tid & 1) * 64;
        #pragma unroll
        for (int j = 0; j < 16; ++j) {
            const float4 v = *reinterpret_cast<const float4*>(&stg[row * PS + off + j * 4]);
            *reinterpret_cast<float4*>(&ob[(size_t)row * HW + off + j * 4]) = v;
        }
        if (pass == 0) { CPA_WAIT(0); }
        __syncthreads();
    }
}

// ---------------------------------------------------------------------------
// K3: sparse GEMM, 3-stage cp.async, ldmatrix.trans for B.
//  grid (2 ct, 4 ks, 32 bb).  Stage s: A hi/lo @ s*71680 + hl*18432;
//  B @ s*71680 + 36864 + hl*17408.  3 stages = 215040 B.
// ---------------------------------------------------------------------------
#define SA3(s, hl) ((s) * 71680 + (hl) * 18432)
#define SB3(s, hl) ((s) * 71680 + 36864 + (hl) * 17408)
#define S_SMEM 215040

__global__ void __launch_bounds__(256, 1)
k_sparse()
{
    extern __shared__ char smem[];
    const uint32_t sb = s2u(smem);
    const int tid = threadIdx.x, wid = tid >> 5, lane = tid & 31;
    const int ct = blockIdx.x, ksp = blockIdx.y, bb = blockIdx.z;
    const int c0 = ct << 7;
    const int pbase = ksp << 10;

    const int wm = (wid >> 1) * 32, wn = (wid & 1) * 64;
    const int lr = lane & 7, lg = lane >> 3;
    const int qrow = lane >> 2, qcol = (lane & 3) * 2;

    float acc[2][8][4];
    #pragma unroll
    for (int mi = 0; mi < 2; ++mi)
        #pragma unroll
        for (int f = 0; f < 8; ++f)
            #pragma unroll
            for (int v = 0; v < 4; ++v) acc[mi][f][v] = 0.f;

    auto fill = [&](int ch, int s) {
        const int pc = pbase + ch * 64;
        #pragma unroll
        for (int i = 0; i < 4; ++i) {
            const int idx = i * 256 + tid;
            const int ro = idx >> 3, sa = idx & 7;
            const uint32_t da = ro * 144 + sa * 16;
            const size_t wo = (size_t)ro * HW + pc + sa * 8;
            CPA16(sb + SA3(s, 0) + da, g_ws1h + wo);
            CPA16(sb + SA3(s, 1) + da, g_ws1l + wo);
            const int rp = idx >> 4, sc = idx & 15;
            const uint32_t db = rp * 272 + sc * 16;
            const size_t fo = ((size_t)bb * HW + pc + rp) * FC + c0 + sc * 8;
            CPA16(sb + SB3(s, 0) + db, g_fh + fo);
            CPA16(sb + SB3(s, 1) + db, g_fl + fo);
        }
        CPA_COMMIT();
    };

    fill(0, 0);
    fill(1, 1);
    #pragma unroll 1
    for (int ch = 0; ch < 16; ++ch) {
        if (ch < 15) { CPA_WAIT(1); } else { CPA_WAIT(0); }
        __syncthreads();
        if (ch + 2 < 16) fill(ch + 2, (ch + 2) % 3);
        const int s = ch % 3;
        #pragma unroll
        for (int ks = 0; ks < 4; ++ks) {
            const int k0 = ks * 16;
            uint32_t ah[2][4], al[2][4];
            #pragma unroll
            for (int mi = 0; mi < 2; ++mi) {
                const uint32_t ad = sb + 2 * ((wm + mi * 16 + lr + ((lg & 1) << 3)) * PK + k0 + ((lg >> 1) << 3));
                LDSM4(ah[mi][0], ah[mi][1], ah[mi][2], ah[mi][3], ad + SA3(s, 0));
                LDSM4(al[mi][0], al[mi][1], al[mi][2], al[mi][3], ad + SA3(s, 1));
            }
            #pragma unroll
            for (int nf = 0; nf < 4; ++nf) {
                uint32_t bh[4], bl[4];
                const uint32_t bd = sb + (k0 + lr + ((lg & 1) << 3)) * 272
                                  + 2 * (wn + nf * 16 + ((lg >> 1) << 3));
                LDSM4T(bh[0], bh[1], bh[2], bh[3], bd + SB3(s, 0));
                LDSM4T(bl[0], bl[1], bl[2], bl[3], bd + SB3(s, 1));
                #pragma unroll
                for (int mi = 0; mi < 2; ++mi)
                    #pragma unroll
                    for (int h = 0; h < 2; ++h) {
                        float* c = acc[mi][nf * 2 + h];
                        mma_bf(c, ah[mi], bh[h * 2], bh[h * 2 + 1]);
                        mma_bf(c, ah[mi], bl[h * 2], bl[h * 2 + 1]);
                        mma_bf(c, al[mi], bh[h * 2], bh[h * 2 + 1]);
                    }
            }
        }
    }
    __syncthreads();

    // stage [c][o] f32, coalesced copy -> g_hsp[ks][bb][c][o]
    float* stg = reinterpret_cast<float*>(smem);
    #pragma unroll
    for (int mi = 0; mi < 2; ++mi)
        #pragma unroll
        for (int f = 0; f < 8; ++f) {
            const int row = wm + mi * 16 + qrow;   // o
            const int col = wn + f * 8 + qcol;     // c (local)
            stg[col * PS + row]           = acc[mi][f][0];
            stg[(col + 1) * PS + row]     = acc[mi][f][1];
            stg[col * PS + row + 8]       = acc[mi][f][2];
            stg[(col + 1) * PS + row + 8] = acc[mi][f][3];
        }
    __syncthreads();
    float* pb = g_hsp + ((size_t)(ksp * NB + bb) * FC + c0) * HSP;
    const int row = tid >> 1, off = (tid & 1) * 64;
    #pragma unroll
    for (int j = 0; j < 16; ++j) {
        const float4 v = *reinterpret_cast<const float4*>(&stg[row * PS + off + j * 4]);
        *reinterpret_cast<float4*>(&pb[(size_t)row * HSP + off + j * 4]) = v;
    }
}

// ---------------------------------------------------------------------------
// K4: fused split-K reduce + bias + relu + sparse layer 2 + embeddings
// ---------------------------------------------------------------------------
__global__ void k_sparse2(const float* __restrict__ b_s1,
                          const float* __restrict__ ws2, const float* __restrict__ bs2,
                          const float* __restrict__ e_neg, const float* __restrict__ e_pos,
                          const int* __restrict__ cls_ids, float* __restrict__ out)
{
    __shared__ float w[NT][HSP];
    __shared__ float bsh[HSP];
    const int bb = blockIdx.x, c = threadIdx.x;
    for (int i = threadIdx.x; i < NT * HSP; i += 256)
        w[i >> 7][i & 127] = ws2[i];
    if (threadIdx.x < HSP) bsh[threadIdx.x] = b_s1[threadIdx.x];
    __syncthreads();

    const bool is64 = (cls_ids[1] == 0) && (cls_ids[3] == 0) &&
                      (cls_ids[5] == 0) && (cls_ids[7] == 0);
    const int cid = is64 ? cls_ids[2 * bb] : cls_ids[bb];
    const float oh = (cid == 1) ? 1.f : 0.f;

    float accs[NT];
    #pragma unroll
    for (int t = 0; t < NT; ++t) accs[t] = 0.f;

    const size_t stride = (size_t)NB * FC * HSP;
    const float4* p0v = reinterpret_cast<const float4*>(g_hsp + ((size_t)bb * FC + c) * HSP);
    const float4* p1v = reinterpret_cast<const float4*>(g_hsp + stride + ((size_t)bb * FC + c) * HSP);
    const float4* p2v = reinterpret_cast<const float4*>(g_hsp + 2 * stride + ((size_t)bb * FC + c) * HSP);
    const float4* p3v = reinterpret_cast<const float4*>(g_hsp + 3 * stride + ((size_t)bb * FC + c) * HSP);
    for (int o4 = 0; o4 < 32; ++o4) {
        const float4 a = p0v[o4], b = p1v[o4], d = p2v[o4], e = p3v[o4];
        const int o = o4 * 4;
        const float h0 = fmaxf(a.x + b.x + d.x + e.x + bsh[o],     0.f);
        const float h1 = fmaxf(a.y + b.y + d.y + e.y + bsh[o + 1], 0.f);
        const float h2 = fmaxf(a.z + b.z + d.z + e.z + bsh[o + 2], 0.f);
        const float h3 = fmaxf(a.w + b.w + d.w + e.w + bsh[o + 3], 0.f);
        #pragma unroll
        for (int t = 0; t < NT; ++t)
            accs[t] += w[t][o]*h0 + w[t][o+1]*h1 + w[t][o+2]*h2 + w[t][o+3]*h3;
    }
    float* ob = out + DENSE_TOTAL + ((size_t)bb * NT) * FC + c;
    #pragma unroll
    for (int t = 0; t < NT; ++t) {
        const float emb = oh * e_pos[t * FC + c] + (1.f - oh) * e_neg[t * FC + c];
        ob[(size_t)t * FC] = accs[t] + bs2[t] + emb;
    }
}

// ---------------------------------------------------------------------------
// Launch
// ---------------------------------------------------------------------------
extern "C" void kernel_launch(void* const* d_in, const int* in_sizes, int n_in,
                              void* d_out, int out_size)
{
    const int off = (n_in >= 14) ? 1 : 0;
    const float* feat  = (const float*)d_in[0];
    const float* proto = (const float*)d_in[1];
    const int*   cls   = (const int*)  d_in[2];
    const float* w_d1  = (const float*)d_in[3 + off];
    const float* b_d1  = (const float*)d_in[4 + off];
    const float* w_d2  = (const float*)d_in[5 + off];
    const float* b_d2  = (const float*)d_in[6 + off];
    const float* w_s1  = (const float*)d_in[7 + off];
    const float* b_s1  = (const float*)d_in[8 + off];
    const float* w_s2  = (const float*)d_in[9 + off];
    const float* b_s2  = (const float*)d_in[10 + off];
    const float* e_neg = (const float*)d_in[11 + off];
    const float* e_pos = (const float*)d_in[12 + off];
    float* out = (float*)d_out;

    cudaFuncSetAttribute(k_dense,  cudaFuncAttributeMaxDynamicSharedMemorySize, D_SMEM);
    cudaFuncSetAttribute(k_sparse, cudaFuncAttributeMaxDynamicSharedMemorySize, S_SMEM);

    k_featprep<<<(NB * HW) / 8, 256>>>(feat, proto);
    k_prep<<<576, 256>>>(w_d1, w_d2, w_s1);
    k_dense<<<NB * (HW / 128), 256, D_SMEM>>>(b_d1, b_d2, out);
    k_sparse<<<dim3(2, SPLIT, NB), 256, S_SMEM>>>();
    k_sparse2<<<NB, 256>>>(b_s1, w_s2, b_s2, e_neg, e_pos, cls, out);
}